// round 16
// baseline (speedup 1.0000x reference)
#include <cuda_runtime.h>

typedef unsigned long long ull;

#define N_REC   200
#define N_INP   10
#define BATCH   256
#define TSTEPS  1000
#define TOTAL_ELEMS 51200000u   // T*B*N

// drive[t][b][r] = { inp_term(t,b,r),  0.01f * normal(t,b,r) }
static __device__ float2 g_drive[TOTAL_ELEMS];

// ---------------------------------------------------------------------------
// helpers
// ---------------------------------------------------------------------------
__device__ __forceinline__ ull ffma2(ull a, ull b, ull c) {
    ull d;
    asm("fma.rn.f32x2 %0, %1, %2, %3;" : "=l"(d) : "l"(a), "l"(b), "l"(c));
    return d;
}
__device__ __forceinline__ float lo32f(ull v) { return __uint_as_float((unsigned)v); }
__device__ __forceinline__ float hi32f(ull v) { return __uint_as_float((unsigned)(v >> 32)); }

__device__ __forceinline__ unsigned rotl32(unsigned v, int s) {
    return __funnelshift_l(v, v, s);
}

// Threefry-2x32/20, key=(0,42), partitionable: counter=(0,p), out = x0^x1.
__device__ __forceinline__ unsigned threefry_bits(unsigned p) {
    const unsigned k0 = 0u;
    const unsigned k1 = 42u;
    const unsigned k2 = 0x1BD11BDAu ^ 0u ^ 42u;
    unsigned x0 = 0u + k0;
    unsigned x1 = p + k1;
#define TFR(rr) { x0 += x1; x1 = rotl32(x1, rr); x1 ^= x0; }
    TFR(13) TFR(15) TFR(26) TFR(6)   x0 += k1; x1 += k2 + 1u;
    TFR(17) TFR(29) TFR(16) TFR(24)  x0 += k2; x1 += k0 + 2u;
    TFR(13) TFR(15) TFR(26) TFR(6)   x0 += k0; x1 += k1 + 3u;
    TFR(17) TFR(29) TFR(16) TFR(24)  x0 += k1; x1 += k2 + 4u;
    TFR(13) TFR(15) TFR(26) TFR(6)   x0 += k2; x1 += k0 + 5u;
#undef TFR
    return x0 ^ x1;
}

// ---------------------------------------------------------------------------
// Pre-kernel: drive[p] = (x·W_inp[r]+b_rec[r], 0.01*N(0,1)).
// x and W_inp rows loaded as float2 (both 8B-aligned: 40B row stride).
// ---------------------------------------------------------------------------
__global__ void gen_drive_kernel(const float* __restrict__ x,
                                 const float* __restrict__ W_inp,
                                 const float* __restrict__ b_rec) {
    unsigned p = blockIdx.x * blockDim.x + threadIdx.x;
    if (p >= TOTAL_ELEMS) return;

    unsigned bits = threefry_bits(p);
    float f = __uint_as_float((bits >> 9) | 0x3f800000u) - 1.0f;   // [0,1)
    const float lo = __uint_as_float(0xbf7fffffu);                 // nextafter(-1,0)
    float u = fmaf(f, 2.0f, lo);
    u = fmaxf(u, lo);
    float n = __uint_as_float(0x3fb504f3u) * erfinvf(u);           // sqrt(2)*erfinv

    unsigned r  = p % 200u;
    unsigned bt = p / 200u;
    unsigned b  = bt & 255u;
    unsigned t  = bt >> 8;
    const float2* xr = reinterpret_cast<const float2*>(
                           x + (b * (unsigned)TSTEPS + t) * (unsigned)N_INP);
    const float2* wr = reinterpret_cast<const float2*>(W_inp + r * (unsigned)N_INP);
    float inp = __ldg(b_rec + r);
#pragma unroll
    for (int i = 0; i < N_INP / 2; ++i) {
        float2 xv = __ldg(xr + i);
        float2 wv = __ldg(wr + i);
        inp = fmaf(xv.x, wv.x, inp);
        inp = fmaf(xv.y, wv.y, inp);
    }

    g_drive[p] = make_float2(inp, 0.01f * n);
}

// ---------------------------------------------------------------------------
// Main persistent RNN kernel: 128 blocks x 896 threads (28 warps).
// 4 warp-aligned k-groups of 7 warps: g = tid/224, lane rl = tid%224.
// Lane holds W_rec[rl, g*50..+50) in 25 ull regs. h in 56-float padded slices
// (16B aligned) -> every inner LDS is a warp-uniform broadcast.
// Sync via producer/consumer named barriers:
//   bar 1: par ready   (g2,g3 arrive non-blocking; g0,g1 sync)
//   bar 2: hs ready    (everyone syncs)
// STG out / LDG drive issued AFTER bar 2 (overlap next dot phase).
// ---------------------------------------------------------------------------
__global__ __launch_bounds__(896, 1)
void rnn_kernel(const float* __restrict__ h0,
                const float* __restrict__ Wrec,
                float* __restrict__ out) {
    __shared__ __align__(16) float hs[2][224];       // [row][slice(rl/50)*56 + rl%50]
    __shared__ __align__(16) float par[2][4][224];   // [row][kgroup][rl]

    const int tid = threadIdx.x;
    const int g   = tid / 224;          // k-group 0..3 (7 warps each)
    const int rl  = tid - g * 224;      // 0..223
    const bool act = (rl < N_REC);
    const int rc  = act ? rl : (N_REC - 1);
    const int b0  = blockIdx.x * 2;

    // ---- W_rec[rc, g*50 .. +50) -> 25 ull regs ----
    ull w[25];
    {
        const ull* wp = reinterpret_cast<const ull*>(Wrec + rc * N_REC + g * 50);
#pragma unroll
        for (int j = 0; j < 25; ++j) w[j] = wp[j];
    }

    const int ws = (rc / 50) * 56 + (rc % 50);   // write slot in padded layout

    // ---- init: groups 0/1 own batch rows b0+0 / b0+1 ----
    float hold = 0.f;
    float2 dr = make_float2(0.f, 0.f);
    if (g < 2 && act) {
        hold = h0[(b0 + g) * N_REC + rl];
        hs[g][ws] = hold;
        dr = g_drive[(unsigned)(b0 + g) * (unsigned)N_REC + (unsigned)rl];
    }
    __syncthreads();

    // epilogue-only pointers (valid for g<2, act)
    float* outp = out + (size_t)(b0 + (g < 2 ? g : 0)) * (TSTEPS * N_REC) + rl;
    const float2* drv = g_drive + ((size_t)BATCH + (size_t)(b0 + (g < 2 ? g : 0)))
                                  * (size_t)N_REC + (size_t)rc;   // t=1 base

    const float* h0p = &hs[0][g * 56];
    const float* h1p = &hs[1][g * 56];
    const ulonglong2* ha = reinterpret_cast<const ulonglong2*>(h0p);
    const ulonglong2* hb = reinterpret_cast<const ulonglong2*>(h1p);

    for (int t = 0; t < TSTEPS; ++t) {
        // ---- partial dot over this group's 50-wide k-slice, both rows ----
        ull a = 0ull, c = 0ull;
#pragma unroll
        for (int j = 0; j < 12; ++j) {
            ulonglong2 va = ha[j];      // warp-uniform broadcast
            ulonglong2 vb = hb[j];
            a = ffma2(w[2 * j],     va.x, a);
            a = ffma2(w[2 * j + 1], va.y, a);
            c = ffma2(w[2 * j],     vb.x, c);
            c = ffma2(w[2 * j + 1], vb.y, c);
        }
        {   // tail: slice floats 48,49
            a = ffma2(w[24], reinterpret_cast<const ull*>(h0p)[24], a);
            c = ffma2(w[24], reinterpret_cast<const ull*>(h1p)[24], c);
        }
        par[0][g][rl] = lo32f(a) + hi32f(a);
        par[1][g][rl] = lo32f(c) + hi32f(c);

        if (g < 2) {
            asm volatile("bar.sync 1, 896;" ::: "memory");   // wait: par ready
            float s = ((par[g][0][rl] + par[g][1][rl]) +
                       (par[g][2][rl] + par[g][3][rl])) + dr.x;
            // tanh(s) = 1 - 2/(exp(2s)+1)
            float e = __expf(s + s);
            float rate = 1.0f - __fdividef(2.0f, e + 1.0f);
            hold = fmaf(0.1f, (rate - hold) + dr.y, hold);
            if (act) hs[g][ws] = hold;
            asm volatile("bar.sync 2, 896;" ::: "memory");   // hs ready
            // off-critical-path: output store + next-step drive prefetch
            if (act) {
                *outp = hold;
                outp += N_REC;
                dr = *drv;                       // drive for t+1
            }
            if (t < TSTEPS - 2) drv += (size_t)BATCH * N_REC;
        } else {
            asm volatile("bar.arrive 1, 896;" ::: "memory"); // producer arrive
            asm volatile("bar.sync 2, 896;"   ::: "memory"); // wait: hs ready
        }
    }
}

// ---------------------------------------------------------------------------
extern "C" void kernel_launch(void* const* d_in, const int* in_sizes, int n_in,
                              void* d_out, int out_size) {
    const float* x     = (const float*)d_in[0];   // [256,1000,10]
    const float* h0    = (const float*)d_in[1];   // [256,200]
    const float* W_inp = (const float*)d_in[2];   // [200,10]
    const float* W_rec = (const float*)d_in[3];   // [200,200]
    const float* b_rec = (const float*)d_in[4];   // [200]
    float* out = (float*)d_out;                   // [256,1000,200]

    gen_drive_kernel<<<TOTAL_ELEMS / 256u, 256>>>(x, W_inp, b_rec);
    rnn_kernel<<<BATCH / 2, 896>>>(h0, W_rec, out);
}

// round 17
// speedup vs baseline: 1.0010x; 1.0010x over previous
#include <cuda_runtime.h>

typedef unsigned long long ull;

#define N_REC   200
#define N_INP   10
#define BATCH   256
#define TSTEPS  1000
#define TOTAL_ELEMS 51200000u   // T*B*N

// drive[t][b][r] = { inp_term(t,b,r),  0.01f * normal(t,b,r) }
static __device__ float2 g_drive[TOTAL_ELEMS];

// ---------------------------------------------------------------------------
// helpers
// ---------------------------------------------------------------------------
__device__ __forceinline__ ull ffma2(ull a, ull b, ull c) {
    ull d;
    asm("fma.rn.f32x2 %0, %1, %2, %3;" : "=l"(d) : "l"(a), "l"(b), "l"(c));
    return d;
}
__device__ __forceinline__ float lo32f(ull v) { return __uint_as_float((unsigned)v); }
__device__ __forceinline__ float hi32f(ull v) { return __uint_as_float((unsigned)(v >> 32)); }

__device__ __forceinline__ unsigned rotl32(unsigned v, int s) {
    return __funnelshift_l(v, v, s);
}

// Threefry-2x32/20, key=(0,42), partitionable: counter=(0,p), out = x0^x1.
__device__ __forceinline__ unsigned threefry_bits(unsigned p) {
    const unsigned k0 = 0u;
    const unsigned k1 = 42u;
    const unsigned k2 = 0x1BD11BDAu ^ 0u ^ 42u;
    unsigned x0 = 0u + k0;
    unsigned x1 = p + k1;
#define TFR(rr) { x0 += x1; x1 = rotl32(x1, rr); x1 ^= x0; }
    TFR(13) TFR(15) TFR(26) TFR(6)   x0 += k1; x1 += k2 + 1u;
    TFR(17) TFR(29) TFR(16) TFR(24)  x0 += k2; x1 += k0 + 2u;
    TFR(13) TFR(15) TFR(26) TFR(6)   x0 += k0; x1 += k1 + 3u;
    TFR(17) TFR(29) TFR(16) TFR(24)  x0 += k1; x1 += k2 + 4u;
    TFR(13) TFR(15) TFR(26) TFR(6)   x0 += k2; x1 += k0 + 5u;
#undef TFR
    return x0 ^ x1;
}

// ---------------------------------------------------------------------------
// Pre-kernel: drive[p] = (x·W_inp[r]+b_rec[r], 0.01*N(0,1)).
// x and W_inp rows loaded as float2 (both 8B-aligned: 40B row stride).
// ---------------------------------------------------------------------------
__global__ void gen_drive_kernel(const float* __restrict__ x,
                                 const float* __restrict__ W_inp,
                                 const float* __restrict__ b_rec) {
    unsigned p = blockIdx.x * blockDim.x + threadIdx.x;
    if (p >= TOTAL_ELEMS) return;

    unsigned bits = threefry_bits(p);
    float f = __uint_as_float((bits >> 9) | 0x3f800000u) - 1.0f;   // [0,1)
    const float lo = __uint_as_float(0xbf7fffffu);                 // nextafter(-1,0)
    float u = fmaf(f, 2.0f, lo);
    u = fmaxf(u, lo);
    float n = __uint_as_float(0x3fb504f3u) * erfinvf(u);           // sqrt(2)*erfinv

    unsigned r  = p % 200u;
    unsigned bt = p / 200u;
    unsigned b  = bt & 255u;
    unsigned t  = bt >> 8;
    const float2* xr = reinterpret_cast<const float2*>(
                           x + (b * (unsigned)TSTEPS + t) * (unsigned)N_INP);
    const float2* wr = reinterpret_cast<const float2*>(W_inp + r * (unsigned)N_INP);
    float inp = __ldg(b_rec + r);
#pragma unroll
    for (int i = 0; i < N_INP / 2; ++i) {
        float2 xv = __ldg(xr + i);
        float2 wv = __ldg(wr + i);
        inp = fmaf(xv.x, wv.x, inp);
        inp = fmaf(xv.y, wv.y, inp);
    }

    g_drive[p] = make_float2(inp, 0.01f * n);
}

// ---------------------------------------------------------------------------
// Main persistent RNN kernel: 128 blocks x 896 threads (28 warps).
// 4 warp-aligned k-groups of 7 warps: g = tid/224, lane rl = tid%224.
// Lane holds W_rec[rl, g*50..+50) in 25 ull regs. h in 56-float padded slices
// (16B aligned) -> every inner LDS is a warp-uniform broadcast.
// Sync via producer/consumer named barriers:
//   bar 1: par ready   (g2,g3 arrive non-blocking; g0,g1 sync)
//   bar 2: hs ready    (everyone syncs)
// STG out / LDG drive issued AFTER bar 2 (overlap next dot phase).
// ---------------------------------------------------------------------------
__global__ __launch_bounds__(896, 1)
void rnn_kernel(const float* __restrict__ h0,
                const float* __restrict__ Wrec,
                float* __restrict__ out) {
    __shared__ __align__(16) float hs[2][224];       // [row][slice(rl/50)*56 + rl%50]
    __shared__ __align__(16) float par[2][4][224];   // [row][kgroup][rl]

    const int tid = threadIdx.x;
    const int g   = tid / 224;          // k-group 0..3 (7 warps each)
    const int rl  = tid - g * 224;      // 0..223
    const bool act = (rl < N_REC);
    const int rc  = act ? rl : (N_REC - 1);
    const int b0  = blockIdx.x * 2;

    // ---- W_rec[rc, g*50 .. +50) -> 25 ull regs ----
    ull w[25];
    {
        const ull* wp = reinterpret_cast<const ull*>(Wrec + rc * N_REC + g * 50);
#pragma unroll
        for (int j = 0; j < 25; ++j) w[j] = wp[j];
    }

    const int ws = (rc / 50) * 56 + (rc % 50);   // write slot in padded layout

    // ---- init: groups 0/1 own batch rows b0+0 / b0+1 ----
    float hold = 0.f;
    float2 dr = make_float2(0.f, 0.f);
    if (g < 2 && act) {
        hold = h0[(b0 + g) * N_REC + rl];
        hs[g][ws] = hold;
        dr = g_drive[(unsigned)(b0 + g) * (unsigned)N_REC + (unsigned)rl];
    }
    __syncthreads();

    // epilogue-only pointers (valid for g<2, act)
    float* outp = out + (size_t)(b0 + (g < 2 ? g : 0)) * (TSTEPS * N_REC) + rl;
    const float2* drv = g_drive + ((size_t)BATCH + (size_t)(b0 + (g < 2 ? g : 0)))
                                  * (size_t)N_REC + (size_t)rc;   // t=1 base

    const float* h0p = &hs[0][g * 56];
    const float* h1p = &hs[1][g * 56];
    const ulonglong2* ha = reinterpret_cast<const ulonglong2*>(h0p);
    const ulonglong2* hb = reinterpret_cast<const ulonglong2*>(h1p);

    for (int t = 0; t < TSTEPS; ++t) {
        // ---- partial dot over this group's 50-wide k-slice, both rows ----
        ull a = 0ull, c = 0ull;
#pragma unroll
        for (int j = 0; j < 12; ++j) {
            ulonglong2 va = ha[j];      // warp-uniform broadcast
            ulonglong2 vb = hb[j];
            a = ffma2(w[2 * j],     va.x, a);
            a = ffma2(w[2 * j + 1], va.y, a);
            c = ffma2(w[2 * j],     vb.x, c);
            c = ffma2(w[2 * j + 1], vb.y, c);
        }
        {   // tail: slice floats 48,49
            a = ffma2(w[24], reinterpret_cast<const ull*>(h0p)[24], a);
            c = ffma2(w[24], reinterpret_cast<const ull*>(h1p)[24], c);
        }
        par[0][g][rl] = lo32f(a) + hi32f(a);
        par[1][g][rl] = lo32f(c) + hi32f(c);

        if (g < 2) {
            asm volatile("bar.sync 1, 896;" ::: "memory");   // wait: par ready
            float s = ((par[g][0][rl] + par[g][1][rl]) +
                       (par[g][2][rl] + par[g][3][rl])) + dr.x;
            // tanh(s) = 1 - 2/(exp(2s)+1)
            float e = __expf(s + s);
            float rate = 1.0f - __fdividef(2.0f, e + 1.0f);
            hold = fmaf(0.1f, (rate - hold) + dr.y, hold);
            if (act) hs[g][ws] = hold;
            asm volatile("bar.sync 2, 896;" ::: "memory");   // hs ready
            // off-critical-path: output store + next-step drive prefetch
            if (act) {
                *outp = hold;
                outp += N_REC;
                dr = *drv;                       // drive for t+1
            }
            if (t < TSTEPS - 2) drv += (size_t)BATCH * N_REC;
        } else {
            asm volatile("bar.arrive 1, 896;" ::: "memory"); // producer arrive
            asm volatile("bar.sync 2, 896;"   ::: "memory"); // wait: hs ready
        }
    }
}

// ---------------------------------------------------------------------------
extern "C" void kernel_launch(void* const* d_in, const int* in_sizes, int n_in,
                              void* d_out, int out_size) {
    const float* x     = (const float*)d_in[0];   // [256,1000,10]
    const float* h0    = (const float*)d_in[1];   // [256,200]
    const float* W_inp = (const float*)d_in[2];   // [200,10]
    const float* W_rec = (const float*)d_in[3];   // [200,200]
    const float* b_rec = (const float*)d_in[4];   // [200]
    float* out = (float*)d_out;                   // [256,1000,200]

    gen_drive_kernel<<<TOTAL_ELEMS / 256u, 256>>>(x, W_inp, b_rec);
    rnn_kernel<<<BATCH / 2, 896>>>(h0, W_rec, out);
}